// round 1
// baseline (speedup 1.0000x reference)
#include <cuda_runtime.h>
#include <math.h>

// Problem constants
#define T_   512
#define N_   1024
#define MC_  512
#define H_   5
#define MW_  20
#define NF_  20
#define KF_  (NF_*MC_)   // 10240
#define HN_  (H_*N_)     // 5120
#define NITER 6

// ---------------- scratch (device globals; no allocation) ----------------
__device__ float g_WWs[(size_t)T_*HN_];     // sigma^(1/4)-weighted spectral window features (T, H*N)
__device__ float g_Ew [(size_t)HN_*MC_];    // E transposed: [(i*N+n), c]
__device__ float g_Kt [(size_t)N_*MC_];     // K transposed: [n, c]
__device__ float g_p  [(size_t)T_*MC_];     // u_pert
__device__ float g_Ft [(size_t)KF_*MC_];    // F transposed: [(f*MC+c'), c] = sum_n Estu[f,c',n]*K[c,n]
__device__ float g_u0 [(size_t)T_*MC_];
__device__ float g_u1 [(size_t)T_*MC_];
__device__ float g_cbuf[(size_t)T_*KF_];    // exclusive cumsum state (T, NF*MC)
__device__ float g_X  [(size_t)T_*N_];
__device__ float g_QX [(size_t)T_*N_];
__device__ float g_RU [(size_t)T_*MC_];
__device__ float g_Csplit[(size_t)8*T_*N_]; // split-K slabs (max 4.19M floats)

// ---------------- kernels ----------------

// WWs[t, i*N+n] = sigma_i^0.25 * sum_k phi[k,i] * W[t+k-(MW-1), n]  (zero-padded)
__global__ void build_WWs(const float* __restrict__ phi, const float* __restrict__ sigma,
                          const float* __restrict__ W)
{
    int t = blockIdx.x;
    for (int idx = threadIdx.x; idx < HN_; idx += blockDim.x) {
        int i = idx / N_, n = idx - i * N_;
        float s4 = sqrtf(sqrtf(sigma[i]));
        float sum = 0.f;
        #pragma unroll
        for (int k = 0; k < MW_; k++) {
            int src = t + k - (MW_ - 1);
            if (src >= 0) sum += phi[k*H_ + i] * W[(size_t)src*N_ + n];
        }
        g_WWs[(size_t)t*HN_ + idx] = s4 * sum;
    }
}

// Ew[(i*N+n), c] = E[c, n, i]   (E is (MC, N, H) row-major)
__global__ void trans_E(const float* __restrict__ E)
{
    int idx = blockIdx.x * blockDim.x + threadIdx.x;
    if (idx >= HN_ * MC_) return;
    int c = idx % MC_;
    int r = idx / MC_;
    int i = r / N_, n = r - i * N_;
    g_Ew[idx] = E[((size_t)c*N_ + n)*H_ + i];
}

// Kt[n, c] = K[c, n]
__global__ void trans_K(const float* __restrict__ Km)
{
    int idx = blockIdx.x * blockDim.x + threadIdx.x;
    if (idx >= N_ * MC_) return;
    int c = idx % MC_;
    int n = idx / MC_;
    g_Kt[idx] = Km[(size_t)c*N_ + n];
}

// Generic fp32 GEMM: C_slab[s] = A[M x K_range_s] * B[K x Nn], row-major, NN.
// BM=BN=128, BK=16, 256 threads, 8x8 accumulators per thread. gridDim.z = splits.
__global__ __launch_bounds__(256) void gemm_nn(
    const float* __restrict__ A, const float* __restrict__ B, float* __restrict__ C,
    int M, int Nn, int K)
{
    const int tid = threadIdx.x;
    const int n0 = blockIdx.x * 128;
    const int m0 = blockIdx.y * 128;
    const int s  = blockIdx.z;
    const int Ks = K / gridDim.z;
    const int kbeg = s * Ks, kend = kbeg + Ks;

    __shared__ float As[16][128];
    __shared__ float Bs[16][128];

    float acc[8][8];
    #pragma unroll
    for (int i = 0; i < 8; i++)
        #pragma unroll
        for (int j = 0; j < 8; j++) acc[i][j] = 0.f;

    const int tx = tid % 16;          // n sub-tile
    const int ty = tid / 16;          // m sub-tile
    const int am  = tid % 128;        // A row within tile
    const int ak4 = (tid / 128) * 4;  // A k quad: 0 or 4 (plus +8 second load)
    const int bn4 = (tid % 32) * 4;   // B col quad
    const int bk  = tid / 32;         // B row 0..7 (plus +8 second load)

    for (int kt = kbeg; kt < kend; kt += 16) {
        float4 a0 = *(const float4*)(A + (size_t)(m0 + am)*K + kt + ak4);
        float4 a1 = *(const float4*)(A + (size_t)(m0 + am)*K + kt + ak4 + 8);
        float4 b0 = *(const float4*)(B + (size_t)(kt + bk    )*Nn + n0 + bn4);
        float4 b1 = *(const float4*)(B + (size_t)(kt + bk + 8)*Nn + n0 + bn4);

        As[ak4+0][am] = a0.x; As[ak4+1][am] = a0.y; As[ak4+2][am] = a0.z; As[ak4+3][am] = a0.w;
        As[ak4+8][am] = a1.x; As[ak4+9][am] = a1.y; As[ak4+10][am] = a1.z; As[ak4+11][am] = a1.w;
        *(float4*)&Bs[bk    ][bn4] = b0;
        *(float4*)&Bs[bk + 8][bn4] = b1;
        __syncthreads();

        #pragma unroll
        for (int kk = 0; kk < 16; kk++) {
            float a[8], b[8];
            *(float4*)(a    ) = *(const float4*)&As[kk][ty*8    ];
            *(float4*)(a + 4) = *(const float4*)&As[kk][ty*8 + 4];
            *(float4*)(b    ) = *(const float4*)&Bs[kk][tx*8    ];
            *(float4*)(b + 4) = *(const float4*)&Bs[kk][tx*8 + 4];
            #pragma unroll
            for (int i = 0; i < 8; i++)
                #pragma unroll
                for (int j = 0; j < 8; j++)
                    acc[i][j] += a[i] * b[j];
        }
        __syncthreads();
    }

    float* Cp = C + (size_t)s*M*Nn + (size_t)(m0 + ty*8)*Nn + n0 + tx*8;
    #pragma unroll
    for (int i = 0; i < 8; i++) {
        *(float4*)(Cp + (size_t)i*Nn    ) = make_float4(acc[i][0], acc[i][1], acc[i][2], acc[i][3]);
        *(float4*)(Cp + (size_t)i*Nn + 4) = make_float4(acc[i][4], acc[i][5], acc[i][6], acc[i][7]);
    }
}

// Deterministic split reduction + epilogue.
// mode 0: out = sum ; mode 1: out = sum + extra[idx % Nn] (bias) ; mode 2: out = extra[idx] - sum
__global__ void reduce_epi(const float* __restrict__ Cs, float* __restrict__ out,
                           const float* __restrict__ extra, int MN, int Nn, int S, int mode)
{
    int i = blockIdx.x * blockDim.x + threadIdx.x;
    if (i >= MN) return;
    float s = 0.f;
    for (int z = 0; z < S; z++) s += Cs[(size_t)z*MN + i];
    if (mode == 0)      out[i] = s;
    else if (mode == 1) out[i] = s + extra[i % Nn];
    else                out[i] = extra[i] - s;
}

__global__ void copy_k(const float* __restrict__ a, float* __restrict__ b, int n)
{
    int i = blockIdx.x * blockDim.x + threadIdx.x;
    if (i < n) b[i] = a[i];
}

// Exclusive time-cumsum: cbuf[t, f*MC+c] = sum_{s<t} phi_stu[s,f] * u[s,c]
__global__ void cumsum_u(const float* __restrict__ u, const float* __restrict__ phis)
{
    int f = blockIdx.y;
    int c = blockIdx.x * 128 + threadIdx.x;
    float acc = 0.f;
    for (int t = 0; t < T_; t++) {
        g_cbuf[(size_t)t*KF_ + f*MC_ + c] = acc;
        acc += phis[t*NF_ + f] * u[(size_t)t*MC_ + c];
    }
}

// losses[t] = dot(X[t], QX[t]) + dot(U[t], RU[t])
__global__ void losses_k(const float* __restrict__ X, const float* __restrict__ QX,
                         const float* __restrict__ U, const float* __restrict__ RU,
                         float* __restrict__ out)
{
    int t = blockIdx.x;
    float s = 0.f;
    for (int n = threadIdx.x; n < N_;  n += 256) s += X[(size_t)t*N_ + n] * QX[(size_t)t*N_ + n];
    for (int c = threadIdx.x; c < MC_; c += 256) s += U[(size_t)t*MC_ + c] * RU[(size_t)t*MC_ + c];
    __shared__ float red[256];
    red[threadIdx.x] = s;
    __syncthreads();
    for (int o = 128; o > 0; o >>= 1) {
        if (threadIdx.x < o) red[threadIdx.x] += red[threadIdx.x + o];
        __syncthreads();
    }
    if (threadIdx.x == 0) out[t] = red[0];
}

// ---------------- host ----------------

extern "C" void kernel_launch(void* const* d_in, const int* in_sizes, int n_in,
                              void* d_out, int out_size)
{
    (void)in_sizes; (void)n_in; (void)out_size;
    const float* Q    = (const float*)d_in[0];
    const float* R    = (const float*)d_in[1];
    const float* Km   = (const float*)d_in[2];
    const float* E    = (const float*)d_in[3];
    const float* bias = (const float*)d_in[4];
    const float* Estu = (const float*)d_in[5];
    const float* phi  = (const float*)d_in[6];
    const float* sig  = (const float*)d_in[7];
    const float* phis = (const float*)d_in[8];
    const float* W    = (const float*)d_in[9];
    float* out = (float*)d_out;

    void *pWWs, *pEw, *pKt, *pP, *pFt, *pU0, *pU1, *pC, *pX, *pQX, *pRU, *pCs;
    cudaGetSymbolAddress(&pWWs, g_WWs);
    cudaGetSymbolAddress(&pEw,  g_Ew);
    cudaGetSymbolAddress(&pKt,  g_Kt);
    cudaGetSymbolAddress(&pP,   g_p);
    cudaGetSymbolAddress(&pFt,  g_Ft);
    cudaGetSymbolAddress(&pU0,  g_u0);
    cudaGetSymbolAddress(&pU1,  g_u1);
    cudaGetSymbolAddress(&pC,   g_cbuf);
    cudaGetSymbolAddress(&pX,   g_X);
    cudaGetSymbolAddress(&pQX,  g_QX);
    cudaGetSymbolAddress(&pRU,  g_RU);
    cudaGetSymbolAddress(&pCs,  g_Csplit);
    float* WWs=(float*)pWWs; float* Ew=(float*)pEw; float* Kt=(float*)pKt;
    float* P=(float*)pP; float* Ft=(float*)pFt; float* U0=(float*)pU0; float* U1=(float*)pU1;
    float* Cb=(float*)pC; float* X=(float*)pX; float* QX=(float*)pQX; float* RU=(float*)pRU;
    float* Cs=(float*)pCs;

    // 1) spectral window features + transposes
    build_WWs<<<T_, 256>>>(phi, sig, W);
    trans_E<<<(HN_*MC_ + 255)/256, 256>>>(E);
    trans_K<<<(N_*MC_ + 255)/256, 256>>>(Km);

    // 2) u_pert = WWs(512x5120) @ Ew(5120x512) + bias     (split-K=8)
    gemm_nn<<<dim3(MC_/128, T_/128, 8), 256>>>(WWs, Ew, Cs, T_, MC_, HN_);
    reduce_epi<<<(T_*MC_ + 255)/256, 256>>>(Cs, P, bias, T_*MC_, MC_, 8, 1);

    // 3) Ft = Estu_flat(10240x1024) @ Kt(1024x512)        (no split; direct write)
    gemm_nn<<<dim3(MC_/128, KF_/128, 1), 256>>>(Estu, Kt, Ft, KF_, MC_, N_);

    // 4) Neumann fixed-point: u <- p - L u  (L strictly lower triangular, ||L||~0.03)
    copy_k<<<(T_*MC_ + 255)/256, 256>>>(P, U0, T_*MC_);
    float* ucur = U0; float* unext = U1;
    for (int it = 0; it < NITER; it++) {
        cumsum_u<<<dim3(MC_/128, NF_), 128>>>(ucur, phis);
        // Lu = cbuf(512x10240) @ Ft(10240x512), split-K=16
        gemm_nn<<<dim3(MC_/128, T_/128, 16), 256>>>(Cb, Ft, Cs, T_, MC_, KF_);
        reduce_epi<<<(T_*MC_ + 255)/256, 256>>>(Cs, unext, P, T_*MC_, MC_, 16, 2);
        float* tmp = ucur; ucur = unext; unext = tmp;
    }
    // after even NITER, converged u is in U0 == ucur

    // 5) states for all t: X = cumsum(u)(512x10240) @ Estu_flat(10240x1024), split-K=8
    cumsum_u<<<dim3(MC_/128, NF_), 128>>>(ucur, phis);
    gemm_nn<<<dim3(N_/128, T_/128, 8), 256>>>(Cb, Estu, Cs, T_, N_, KF_);
    reduce_epi<<<(T_*N_ + 255)/256, 256>>>(Cs, X, nullptr, T_*N_, N_, 8, 0);

    // 6) quadratic forms (general Q, R)
    gemm_nn<<<dim3(N_/128, T_/128, 4), 256>>>(X, Q, Cs, T_, N_, N_);
    reduce_epi<<<(T_*N_ + 255)/256, 256>>>(Cs, QX, nullptr, T_*N_, N_, 4, 0);
    gemm_nn<<<dim3(MC_/128, T_/128, 4), 256>>>(ucur, R, Cs, T_, MC_, MC_);
    reduce_epi<<<(T_*MC_ + 255)/256, 256>>>(Cs, RU, nullptr, T_*MC_, MC_, 4, 0);

    // 7) losses
    losses_k<<<T_, 256>>>(X, QX, ucur, RU, out);
}

// round 2
// speedup vs baseline: 1.1526x; 1.1526x over previous
#include <cuda_runtime.h>
#include <math.h>

// Problem constants
#define T_   512
#define N_   1024
#define MC_  512
#define H_   5
#define MW_  20
#define NF_  20
#define KF_  (NF_*MC_)   // 10240
#define HN_  (H_*N_)     // 5120
#define NITER 4

// ---------------- scratch (device globals; no allocation) ----------------
__device__ float g_WWs[(size_t)T_*HN_];
__device__ float g_Ew [(size_t)HN_*MC_];
__device__ float g_Kt [(size_t)N_*MC_];
__device__ float g_p  [(size_t)T_*MC_];
__device__ float g_Ft [(size_t)KF_*MC_];
__device__ float g_u0 [(size_t)T_*MC_];
__device__ float g_u1 [(size_t)T_*MC_];
__device__ float g_cbuf[(size_t)T_*KF_];
__device__ float g_X  [(size_t)T_*N_];
__device__ float g_QX [(size_t)T_*N_];
__device__ float g_RU [(size_t)T_*MC_];
__device__ float g_Csplit[(size_t)16*T_*512]; // split-K slabs (4.19M floats)

// ---------------- small kernels ----------------

__global__ void build_WWs(const float* __restrict__ phi, const float* __restrict__ sigma,
                          const float* __restrict__ W)
{
    int t = blockIdx.x;
    for (int idx = threadIdx.x; idx < HN_; idx += blockDim.x) {
        int i = idx / N_, n = idx - i * N_;
        float s4 = sqrtf(sqrtf(sigma[i]));
        float sum = 0.f;
        #pragma unroll
        for (int k = 0; k < MW_; k++) {
            int src = t + k - (MW_ - 1);
            if (src >= 0) sum += phi[k*H_ + i] * W[(size_t)src*N_ + n];
        }
        g_WWs[(size_t)t*HN_ + idx] = s4 * sum;
    }
}

__global__ void trans_E(const float* __restrict__ E)
{
    int idx = blockIdx.x * blockDim.x + threadIdx.x;
    if (idx >= HN_ * MC_) return;
    int c = idx % MC_;
    int r = idx / MC_;
    int i = r / N_, n = r - i * N_;
    g_Ew[idx] = E[((size_t)c*N_ + n)*H_ + i];
}

__global__ void trans_K(const float* __restrict__ Km)
{
    int idx = blockIdx.x * blockDim.x + threadIdx.x;
    if (idx >= N_ * MC_) return;
    int c = idx % MC_;
    int n = idx / MC_;
    g_Kt[idx] = Km[(size_t)c*N_ + n];
}

// ---------------- FFMA2 GEMM ----------------
// C_slab[s] = A[M x Ks] * B[K x Nn], row-major NN. 128x128x16 tiles, 256 thr,
// 8x8 per-thread accumulators held as 8x4 packed f32x2 (fma.rn.f32x2).

__device__ __forceinline__ unsigned long long pack_dup(float v) {
    unsigned int b = __float_as_uint(v);
    return (unsigned long long)b | ((unsigned long long)b << 32);
}

__global__ __launch_bounds__(256, 2) void gemm_nn(
    const float* __restrict__ A, const float* __restrict__ B, float* __restrict__ C,
    int M, int Nn, int K)
{
    const int tid = threadIdx.x;
    const int n0 = blockIdx.x * 128;
    const int m0 = blockIdx.y * 128;
    const int s  = blockIdx.z;
    const int Ks = K / gridDim.z;
    const int kbeg = s * Ks, kend = kbeg + Ks;

    __shared__ unsigned long long As2[16][128];  // A value duplicated into both f32x2 lanes
    __shared__ float Bs[16][128];

    unsigned long long acc[8][4];
    #pragma unroll
    for (int i = 0; i < 8; i++)
        #pragma unroll
        for (int j = 0; j < 4; j++) acc[i][j] = 0ull;

    const int tx = tid % 16;          // n sub-tile
    const int ty = tid / 16;          // m sub-tile
    const int am  = tid % 128;        // A row within tile
    const int ak4 = (tid / 128) * 4;  // A k quad: 0 or 4 (plus +8 second load)
    const int bn4 = (tid % 32) * 4;   // B col quad
    const int bk  = tid / 32;         // B row 0..7 (plus +8 second load)

    const float* Ap = A + (size_t)(m0 + am)*K + ak4;
    const float* Bp = B + (size_t)bk*Nn + n0 + bn4;

    // prefetch first tile
    float4 pa0 = *(const float4*)(Ap + kbeg);
    float4 pa1 = *(const float4*)(Ap + kbeg + 8);
    float4 pb0 = *(const float4*)(Bp + (size_t)kbeg*Nn);
    float4 pb1 = *(const float4*)(Bp + (size_t)(kbeg + 8)*Nn);

    for (int kt = kbeg; kt < kend; kt += 16) {
        // store staged tile to smem
        As2[ak4+0][am] = pack_dup(pa0.x); As2[ak4+1][am] = pack_dup(pa0.y);
        As2[ak4+2][am] = pack_dup(pa0.z); As2[ak4+3][am] = pack_dup(pa0.w);
        As2[ak4+8][am] = pack_dup(pa1.x); As2[ak4+9][am] = pack_dup(pa1.y);
        As2[ak4+10][am] = pack_dup(pa1.z); As2[ak4+11][am] = pack_dup(pa1.w);
        *(float4*)&Bs[bk    ][bn4] = pb0;
        *(float4*)&Bs[bk + 8][bn4] = pb1;
        __syncthreads();

        const bool has_next = (kt + 16) < kend;
        if (has_next) {  // overlap next-tile LDG with compute
            pa0 = *(const float4*)(Ap + kt + 16);
            pa1 = *(const float4*)(Ap + kt + 24);
            pb0 = *(const float4*)(Bp + (size_t)(kt + 16)*Nn);
            pb1 = *(const float4*)(Bp + (size_t)(kt + 24)*Nn);
        }

        #pragma unroll
        for (int kk = 0; kk < 16; kk++) {
            unsigned long long a2[8], b2[4];
            *(ulonglong2*)(a2    ) = *(const ulonglong2*)&As2[kk][ty*8    ];
            *(ulonglong2*)(a2 + 2) = *(const ulonglong2*)&As2[kk][ty*8 + 2];
            *(ulonglong2*)(a2 + 4) = *(const ulonglong2*)&As2[kk][ty*8 + 4];
            *(ulonglong2*)(a2 + 6) = *(const ulonglong2*)&As2[kk][ty*8 + 6];
            *(ulonglong2*)(b2    ) = *(const ulonglong2*)&Bs[kk][tx*8    ];
            *(ulonglong2*)(b2 + 2) = *(const ulonglong2*)&Bs[kk][tx*8 + 4];
            #pragma unroll
            for (int i = 0; i < 8; i++)
                #pragma unroll
                for (int j = 0; j < 4; j++)
                    asm("fma.rn.f32x2 %0, %1, %2, %0;"
                        : "+l"(acc[i][j]) : "l"(a2[i]), "l"(b2[j]));
        }
        __syncthreads();
    }

    float* Cp = C + (size_t)s*M*Nn + (size_t)(m0 + ty*8)*Nn + n0 + tx*8;
    #pragma unroll
    for (int i = 0; i < 8; i++) {
        float4 v0, v1;
        v0.x = __uint_as_float((unsigned int)(acc[i][0]));
        v0.y = __uint_as_float((unsigned int)(acc[i][0] >> 32));
        v0.z = __uint_as_float((unsigned int)(acc[i][1]));
        v0.w = __uint_as_float((unsigned int)(acc[i][1] >> 32));
        v1.x = __uint_as_float((unsigned int)(acc[i][2]));
        v1.y = __uint_as_float((unsigned int)(acc[i][2] >> 32));
        v1.z = __uint_as_float((unsigned int)(acc[i][3]));
        v1.w = __uint_as_float((unsigned int)(acc[i][3] >> 32));
        *(float4*)(Cp + (size_t)i*Nn    ) = v0;
        *(float4*)(Cp + (size_t)i*Nn + 4) = v1;
    }
}

// Deterministic split reduction + epilogue.
// mode 0: out = sum ; mode 1: out = sum + extra[idx % Nn] ; mode 2: out = extra[idx] - sum
__global__ void reduce_epi(const float* __restrict__ Cs, float* __restrict__ out,
                           const float* __restrict__ extra, int MN, int Nn, int S, int mode)
{
    int i = blockIdx.x * blockDim.x + threadIdx.x;
    if (i >= MN) return;
    float s = 0.f;
    for (int z = 0; z < S; z++) s += Cs[(size_t)z*MN + i];
    if (mode == 0)      out[i] = s;
    else if (mode == 1) out[i] = s + extra[i % Nn];
    else                out[i] = extra[i] - s;
}

__global__ void copy_k(const float* __restrict__ a, float* __restrict__ b, int n)
{
    int i = blockIdx.x * blockDim.x + threadIdx.x;
    if (i < n) b[i] = a[i];
}

// Exclusive time-cumsum: cbuf[t, f*MC+c] = sum_{s<t} phi_stu[s,f] * u[s,c]
__global__ void cumsum_u(const float* __restrict__ u, const float* __restrict__ phis)
{
    int f = blockIdx.y;
    int c = blockIdx.x * 128 + threadIdx.x;
    float acc = 0.f;
    for (int t = 0; t < T_; t++) {
        g_cbuf[(size_t)t*KF_ + f*MC_ + c] = acc;
        acc += phis[t*NF_ + f] * u[(size_t)t*MC_ + c];
    }
}

// losses[t] = dot(X[t], QX[t]) + dot(U[t], RU[t])
__global__ void losses_k(const float* __restrict__ X, const float* __restrict__ QX,
                         const float* __restrict__ U, const float* __restrict__ RU,
                         float* __restrict__ out)
{
    int t = blockIdx.x;
    float s = 0.f;
    for (int n = threadIdx.x; n < N_;  n += 256) s += X[(size_t)t*N_ + n] * QX[(size_t)t*N_ + n];
    for (int c = threadIdx.x; c < MC_; c += 256) s += U[(size_t)t*MC_ + c] * RU[(size_t)t*MC_ + c];
    __shared__ float red[256];
    red[threadIdx.x] = s;
    __syncthreads();
    for (int o = 128; o > 0; o >>= 1) {
        if (threadIdx.x < o) red[threadIdx.x] += red[threadIdx.x + o];
        __syncthreads();
    }
    if (threadIdx.x == 0) out[t] = red[0];
}

// ---------------- host ----------------

extern "C" void kernel_launch(void* const* d_in, const int* in_sizes, int n_in,
                              void* d_out, int out_size)
{
    (void)in_sizes; (void)n_in; (void)out_size;
    const float* Q    = (const float*)d_in[0];
    const float* R    = (const float*)d_in[1];
    const float* Km   = (const float*)d_in[2];
    const float* E    = (const float*)d_in[3];
    const float* bias = (const float*)d_in[4];
    const float* Estu = (const float*)d_in[5];
    const float* phi  = (const float*)d_in[6];
    const float* sig  = (const float*)d_in[7];
    const float* phis = (const float*)d_in[8];
    const float* W    = (const float*)d_in[9];
    float* out = (float*)d_out;

    void *pWWs, *pEw, *pKt, *pP, *pFt, *pU0, *pU1, *pC, *pX, *pQX, *pRU, *pCs;
    cudaGetSymbolAddress(&pWWs, g_WWs);
    cudaGetSymbolAddress(&pEw,  g_Ew);
    cudaGetSymbolAddress(&pKt,  g_Kt);
    cudaGetSymbolAddress(&pP,   g_p);
    cudaGetSymbolAddress(&pFt,  g_Ft);
    cudaGetSymbolAddress(&pU0,  g_u0);
    cudaGetSymbolAddress(&pU1,  g_u1);
    cudaGetSymbolAddress(&pC,   g_cbuf);
    cudaGetSymbolAddress(&pX,   g_X);
    cudaGetSymbolAddress(&pQX,  g_QX);
    cudaGetSymbolAddress(&pRU,  g_RU);
    cudaGetSymbolAddress(&pCs,  g_Csplit);
    float* WWs=(float*)pWWs; float* Ew=(float*)pEw; float* Kt=(float*)pKt;
    float* P=(float*)pP; float* Ft=(float*)pFt; float* U0=(float*)pU0; float* U1=(float*)pU1;
    float* Cb=(float*)pC; float* X=(float*)pX; float* QX=(float*)pQX; float* RU=(float*)pRU;
    float* Cs=(float*)pCs;

    // 1) spectral window features + transposes
    build_WWs<<<T_, 256>>>(phi, sig, W);
    trans_E<<<(HN_*MC_ + 255)/256, 256>>>(E);
    trans_K<<<(N_*MC_ + 255)/256, 256>>>(Km);

    // 2) u_pert = WWs(512x5120) @ Ew(5120x512) + bias   (split-K=16 -> grid 256)
    gemm_nn<<<dim3(MC_/128, T_/128, 16), 256>>>(WWs, Ew, Cs, T_, MC_, HN_);
    reduce_epi<<<(T_*MC_ + 255)/256, 256>>>(Cs, P, bias, T_*MC_, MC_, 16, 1);

    // 3) Ft = Estu_flat(10240x1024) @ Kt(1024x512)      (grid 320, direct write)
    gemm_nn<<<dim3(MC_/128, KF_/128, 1), 256>>>(Estu, Kt, Ft, KF_, MC_, N_);

    // 4) Neumann fixed-point: u <- p - L u
    copy_k<<<(T_*MC_ + 255)/256, 256>>>(P, U0, T_*MC_);
    float* ucur = U0; float* unext = U1;
    for (int it = 0; it < NITER; it++) {
        cumsum_u<<<dim3(MC_/128, NF_), 128>>>(ucur, phis);
        gemm_nn<<<dim3(MC_/128, T_/128, 16), 256>>>(Cb, Ft, Cs, T_, MC_, KF_);
        reduce_epi<<<(T_*MC_ + 255)/256, 256>>>(Cs, unext, P, T_*MC_, MC_, 16, 2);
        float* tmp = ucur; ucur = unext; unext = tmp;
    }

    // 5) X = cumsum(u)(512x10240) @ Estu_flat(10240x1024)  (split-K=8 -> grid 256)
    cumsum_u<<<dim3(MC_/128, NF_), 128>>>(ucur, phis);
    gemm_nn<<<dim3(N_/128, T_/128, 8), 256>>>(Cb, Estu, Cs, T_, N_, KF_);
    reduce_epi<<<(T_*N_ + 255)/256, 256>>>(Cs, X, nullptr, T_*N_, N_, 8, 0);

    // 6) quadratic forms (general Q, R)
    gemm_nn<<<dim3(N_/128, T_/128, 8), 256>>>(X, Q, Cs, T_, N_, N_);
    reduce_epi<<<(T_*N_ + 255)/256, 256>>>(Cs, QX, nullptr, T_*N_, N_, 8, 0);
    gemm_nn<<<dim3(MC_/128, T_/128, 8), 256>>>(ucur, R, Cs, T_, MC_, MC_);
    reduce_epi<<<(T_*MC_ + 255)/256, 256>>>(Cs, RU, nullptr, T_*MC_, MC_, 8, 0);

    // 7) losses
    losses_k<<<T_, 256>>>(X, QX, ucur, RU, out);
}

// round 3
// speedup vs baseline: 2.5556x; 2.2172x over previous
#include <cuda_runtime.h>
#include <cuda_bf16.h>
#include <math.h>
#include <stdint.h>

#define T_   512
#define N_   1024
#define MC_  512
#define H_   5
#define MW_  20
#define NF_  20
#define KF_  (NF_*MC_)   // 10240
#define HN_  (H_*N_)     // 5120
#define NITER 4

typedef __nv_bfloat16 bf16;

// ---------------- device scratch ----------------
__device__ bf16  g_WWs_h[(size_t)T_*HN_],  g_WWs_l[(size_t)T_*HN_];
__device__ bf16  g_Ew_h [(size_t)MC_*HN_], g_Ew_l [(size_t)MC_*HN_];
__device__ bf16  g_Km_h [(size_t)MC_*N_],  g_Km_l [(size_t)MC_*N_];
__device__ bf16  g_Es_h [(size_t)KF_*N_],  g_Es_l [(size_t)KF_*N_];   // Estu flat split (B of Ft)
__device__ bf16  g_EsT_h[(size_t)N_*KF_],  g_EsT_l[(size_t)N_*KF_];   // Estu transposed (B of X)
__device__ bf16  g_Qt_h [(size_t)N_*N_],   g_Qt_l [(size_t)N_*N_];
__device__ bf16  g_Rt_h [(size_t)MC_*MC_], g_Rt_l [(size_t)MC_*MC_];
__device__ bf16  g_Ft_h [(size_t)MC_*KF_], g_Ft_l [(size_t)MC_*KF_];
__device__ bf16  g_cb_h [(size_t)T_*KF_],  g_cb_l [(size_t)T_*KF_];
__device__ bf16  g_X_h  [(size_t)T_*N_],   g_X_l  [(size_t)T_*N_];
__device__ bf16  g_u_h  [(size_t)T_*MC_],  g_u_l  [(size_t)T_*MC_];
__device__ float g_P   [(size_t)T_*MC_];
__device__ float g_u0  [(size_t)T_*MC_];
__device__ float g_u1  [(size_t)T_*MC_];
__device__ float g_X   [(size_t)T_*N_];
__device__ float g_QX  [(size_t)T_*N_];
__device__ float g_RU  [(size_t)T_*MC_];
__device__ float g_Cs  [(size_t)MC_*KF_]; // split-K slabs / Ft f32 staging (5.24M floats)

__device__ __forceinline__ void split2(float x, bf16& h, bf16& l) {
    h = __float2bfloat16(x);
    l = __float2bfloat16(x - __bfloat162float(h));
}

// ---------------- producers ----------------

__global__ void build_WWs(const float* __restrict__ phi, const float* __restrict__ sigma,
                          const float* __restrict__ W)
{
    int t = blockIdx.x;
    for (int idx = threadIdx.x; idx < HN_; idx += blockDim.x) {
        int i = idx / N_, n = idx - i * N_;
        float s4 = sqrtf(sqrtf(sigma[i]));
        float sum = 0.f;
        #pragma unroll
        for (int k = 0; k < MW_; k++) {
            int src = t + k - (MW_ - 1);
            if (src >= 0) sum += phi[k*H_ + i] * W[(size_t)src*N_ + n];
        }
        split2(s4 * sum, g_WWs_h[(size_t)t*HN_ + idx], g_WWs_l[(size_t)t*HN_ + idx]);
    }
}

// Ew[c][i*N+n] = E[c,n,i]   (E is (MC,N,H) row-major)
__global__ void build_Ew(const float* __restrict__ E)
{
    int idx = blockIdx.x * blockDim.x + threadIdx.x;
    if (idx >= MC_ * HN_) return;
    int c = idx / HN_, k = idx - c * HN_;
    int i = k / N_, n = k - i * N_;
    split2(E[((size_t)c*N_ + n)*H_ + i], g_Ew_h[idx], g_Ew_l[idx]);
}

__global__ void split_arr(const float* __restrict__ in, bf16* __restrict__ oh,
                          bf16* __restrict__ ol, int n)
{
    int i = blockIdx.x * blockDim.x + threadIdx.x;
    if (i < n) split2(in[i], oh[i], ol[i]);
}

// out[c][r] = in[r][c] (tiled transpose + split). rows, cols multiples of 32.
__global__ void transpose_split(const float* __restrict__ in, bf16* __restrict__ oh,
                                bf16* __restrict__ ol, int rows, int cols)
{
    __shared__ float tile[32][33];
    int c0 = blockIdx.x * 32, r0 = blockIdx.y * 32;
    for (int dy = threadIdx.y; dy < 32; dy += 8)
        tile[dy][threadIdx.x] = in[(size_t)(r0 + dy)*cols + c0 + threadIdx.x];
    __syncthreads();
    for (int dy = threadIdx.y; dy < 32; dy += 8) {
        size_t o = (size_t)(c0 + dy)*rows + r0 + threadIdx.x;
        split2(tile[threadIdx.x][dy], oh[o], ol[o]);
    }
}

// Exclusive time-cumsum -> split bf16: cb[t][f*MC+c] = sum_{s<t} phis[s,f]*u[s,c]
__global__ void cumsum_u(const float* __restrict__ u, const float* __restrict__ phis)
{
    int f = blockIdx.y;
    int c = blockIdx.x * 128 + threadIdx.x;
    float acc = 0.f;
    for (int t = 0; t < T_; t++) {
        size_t o = (size_t)t*KF_ + f*MC_ + c;
        split2(acc, g_cb_h[o], g_cb_l[o]);
        acc += phis[t*NF_ + f] * u[(size_t)t*MC_ + c];
    }
}

// ---------------- mma.sync bf16 GEMM ----------------
// D_slab[z] = A[M,Kz] * B^T where B stored [Nn,K] k-major. 128x128 CTA tile,
// BK=16, 256 thr (8 warps = 4m x 2n), warp tile 32x64, mma m16n8k16.

__device__ __forceinline__ void mma16816(float* c, const uint32_t* a, uint32_t b0, uint32_t b1)
{
    asm volatile(
        "mma.sync.aligned.m16n8k16.row.col.f32.bf16.bf16.f32 "
        "{%0,%1,%2,%3}, {%4,%5,%6,%7}, {%8,%9}, {%0,%1,%2,%3};"
        : "+f"(c[0]), "+f"(c[1]), "+f"(c[2]), "+f"(c[3])
        : "r"(a[0]), "r"(a[1]), "r"(a[2]), "r"(a[3]), "r"(b0), "r"(b1));
}

template<int NPROD>
__global__ __launch_bounds__(256, 2) void gemm_mma(
    const bf16* __restrict__ Ah, const bf16* __restrict__ Al,
    const bf16* __restrict__ Bh, const bf16* __restrict__ Bl,
    float* __restrict__ C, int M, int Nn, int K)
{
    const int tid = threadIdx.x;
    const int wid = tid >> 5, lane = tid & 31;
    const int g = lane >> 2, tg = lane & 3;
    const int n0 = blockIdx.x * 128, m0 = blockIdx.y * 128;
    const int Ks = K / gridDim.z;
    const int kbeg = blockIdx.z * Ks;
    const int warp_m = (wid >> 1) * 32, warp_n = (wid & 1) * 64;

    __shared__ bf16 Ash[2][128][24];
    __shared__ bf16 Bsh[2][128][24];

    float acc[2][8][4];
    #pragma unroll
    for (int i = 0; i < 2; i++)
        #pragma unroll
        for (int j = 0; j < 8; j++)
            #pragma unroll
            for (int q = 0; q < 4; q++) acc[i][j][q] = 0.f;

    const int lrow = tid >> 1, lk = (tid & 1) * 8;
    const bf16* Aph = Ah + (size_t)(m0 + lrow)*K + kbeg + lk;
    const bf16* Bph = Bh + (size_t)(n0 + lrow)*K + kbeg + lk;
    const bf16* Apl = (NPROD == 3) ? Al + (size_t)(m0 + lrow)*K + kbeg + lk : Aph;
    const bf16* Bpl = (NPROD == 3) ? Bl + (size_t)(n0 + lrow)*K + kbeg + lk : Bph;

    uint4 sA0, sB0, sA1, sB1;
    sA0 = *(const uint4*)Aph;
    sB0 = *(const uint4*)Bph;
    if (NPROD == 3) { sA1 = *(const uint4*)Apl; sB1 = *(const uint4*)Bpl; }

    for (int kt = 0; kt < Ks; kt += 16) {
        *(uint4*)&Ash[0][lrow][lk] = sA0;
        *(uint4*)&Bsh[0][lrow][lk] = sB0;
        if (NPROD == 3) {
            *(uint4*)&Ash[1][lrow][lk] = sA1;
            *(uint4*)&Bsh[1][lrow][lk] = sB1;
        }
        __syncthreads();

        if (kt + 16 < Ks) {
            sA0 = *(const uint4*)(Aph + kt + 16);
            sB0 = *(const uint4*)(Bph + kt + 16);
            if (NPROD == 3) {
                sA1 = *(const uint4*)(Apl + kt + 16);
                sB1 = *(const uint4*)(Bpl + kt + 16);
            }
        }

        uint32_t ah[2][4], al[2][4];
        #pragma unroll
        for (int mt = 0; mt < 2; mt++) {
            int r = warp_m + mt*16 + g;
            ah[mt][0] = *(const uint32_t*)&Ash[0][r    ][2*tg    ];
            ah[mt][1] = *(const uint32_t*)&Ash[0][r + 8][2*tg    ];
            ah[mt][2] = *(const uint32_t*)&Ash[0][r    ][2*tg + 8];
            ah[mt][3] = *(const uint32_t*)&Ash[0][r + 8][2*tg + 8];
            if (NPROD == 3) {
                al[mt][0] = *(const uint32_t*)&Ash[1][r    ][2*tg    ];
                al[mt][1] = *(const uint32_t*)&Ash[1][r + 8][2*tg    ];
                al[mt][2] = *(const uint32_t*)&Ash[1][r    ][2*tg + 8];
                al[mt][3] = *(const uint32_t*)&Ash[1][r + 8][2*tg + 8];
            }
        }
        #pragma unroll
        for (int nt = 0; nt < 8; nt++) {
            int nr = warp_n + nt*8 + g;
            uint32_t bh0 = *(const uint32_t*)&Bsh[0][nr][2*tg    ];
            uint32_t bh1 = *(const uint32_t*)&Bsh[0][nr][2*tg + 8];
            #pragma unroll
            for (int mt = 0; mt < 2; mt++)
                mma16816(acc[mt][nt], ah[mt], bh0, bh1);
            if (NPROD == 3) {
                uint32_t bl0 = *(const uint32_t*)&Bsh[1][nr][2*tg    ];
                uint32_t bl1 = *(const uint32_t*)&Bsh[1][nr][2*tg + 8];
                #pragma unroll
                for (int mt = 0; mt < 2; mt++) {
                    mma16816(acc[mt][nt], ah[mt], bl0, bl1);
                    mma16816(acc[mt][nt], al[mt], bh0, bh1);
                }
            }
        }
        __syncthreads();
    }

    float* Cb = C + (size_t)blockIdx.z * M * Nn;
    #pragma unroll
    for (int mt = 0; mt < 2; mt++) {
        #pragma unroll
        for (int nt = 0; nt < 8; nt++) {
            int row = m0 + warp_m + mt*16 + g;
            int col = n0 + warp_n + nt*8 + 2*tg;
            *(float2*)&Cb[(size_t)row*Nn + col]     = make_float2(acc[mt][nt][0], acc[mt][nt][1]);
            *(float2*)&Cb[(size_t)(row+8)*Nn + col] = make_float2(acc[mt][nt][2], acc[mt][nt][3]);
        }
    }
}

// ---------------- reductions / epilogues ----------------
// mode 0: out=sum ; 1: out=sum+extra[i%Nn] ; 2: out=extra[i]-sum
__global__ void reduce_epi(const float* __restrict__ Cs, float* __restrict__ out,
                           const float* __restrict__ extra, int MN, int Nn, int S, int mode)
{
    int i = blockIdx.x * blockDim.x + threadIdx.x;
    if (i >= MN) return;
    float s = 0.f;
    for (int z = 0; z < S; z++) s += Cs[(size_t)z*MN + i];
    if (mode == 0)      out[i] = s;
    else if (mode == 1) out[i] = s + extra[i % Nn];
    else                out[i] = extra[i] - s;
}

// sum slabs -> f32 + split bf16 (for X)
__global__ void reduce_split(const float* __restrict__ Cs, float* __restrict__ out,
                             bf16* __restrict__ oh, bf16* __restrict__ ol, int MN, int S)
{
    int i = blockIdx.x * blockDim.x + threadIdx.x;
    if (i >= MN) return;
    float s = 0.f;
    for (int z = 0; z < S; z++) s += Cs[(size_t)z*MN + i];
    out[i] = s;
    split2(s, oh[i], ol[i]);
}

__global__ void copy_k(const float* __restrict__ a, float* __restrict__ b, int n)
{
    int i = blockIdx.x * blockDim.x + threadIdx.x;
    if (i < n) b[i] = a[i];
}

__global__ void losses_k(const float* __restrict__ X, const float* __restrict__ QX,
                         const float* __restrict__ U, const float* __restrict__ RU,
                         float* __restrict__ out)
{
    int t = blockIdx.x;
    float s = 0.f;
    for (int n = threadIdx.x; n < N_;  n += 256) s += X[(size_t)t*N_ + n] * QX[(size_t)t*N_ + n];
    for (int c = threadIdx.x; c < MC_; c += 256) s += U[(size_t)t*MC_ + c] * RU[(size_t)t*MC_ + c];
    __shared__ float red[256];
    red[threadIdx.x] = s;
    __syncthreads();
    for (int o = 128; o > 0; o >>= 1) {
        if (threadIdx.x < o) red[threadIdx.x] += red[threadIdx.x + o];
        __syncthreads();
    }
    if (threadIdx.x == 0) out[t] = red[0];
}

// ---------------- host ----------------

template<typename Tp> static Tp* sym(const void* s) { void* p; cudaGetSymbolAddress(&p, s); return (Tp*)p; }

extern "C" void kernel_launch(void* const* d_in, const int* in_sizes, int n_in,
                              void* d_out, int out_size)
{
    (void)in_sizes; (void)n_in; (void)out_size;
    const float* Q    = (const float*)d_in[0];
    const float* R    = (const float*)d_in[1];
    const float* Km   = (const float*)d_in[2];
    const float* E    = (const float*)d_in[3];
    const float* bias = (const float*)d_in[4];
    const float* Estu = (const float*)d_in[5];
    const float* phi  = (const float*)d_in[6];
    const float* sig  = (const float*)d_in[7];
    const float* phis = (const float*)d_in[8];
    const float* W    = (const float*)d_in[9];
    float* out = (float*)d_out;

    bf16 *WWs_h = sym<bf16>(g_WWs_h), *WWs_l = sym<bf16>(g_WWs_l);
    bf16 *Ew_h  = sym<bf16>(g_Ew_h),  *Ew_l  = sym<bf16>(g_Ew_l);
    bf16 *Km_h  = sym<bf16>(g_Km_h),  *Km_l  = sym<bf16>(g_Km_l);
    bf16 *Es_h  = sym<bf16>(g_Es_h),  *Es_l  = sym<bf16>(g_Es_l);
    bf16 *EsT_h = sym<bf16>(g_EsT_h), *EsT_l = sym<bf16>(g_EsT_l);
    bf16 *Qt_h  = sym<bf16>(g_Qt_h),  *Qt_l  = sym<bf16>(g_Qt_l);
    bf16 *Rt_h  = sym<bf16>(g_Rt_h),  *Rt_l  = sym<bf16>(g_Rt_l);
    bf16 *Ft_h  = sym<bf16>(g_Ft_h),  *Ft_l  = sym<bf16>(g_Ft_l);
    bf16 *cb_h  = sym<bf16>(g_cb_h),  *cb_l  = sym<bf16>(g_cb_l);
    bf16 *X_h   = sym<bf16>(g_X_h),   *X_l   = sym<bf16>(g_X_l);
    bf16 *u_h   = sym<bf16>(g_u_h),   *u_l   = sym<bf16>(g_u_l);
    float *P  = sym<float>(g_P),  *U0 = sym<float>(g_u0), *U1 = sym<float>(g_u1);
    float *X  = sym<float>(g_X),  *QX = sym<float>(g_QX), *RU = sym<float>(g_RU);
    float *Cs = sym<float>(g_Cs);

    // ---- one-time operand prep ----
    build_WWs<<<T_, 256>>>(phi, sig, W);
    build_Ew<<<(MC_*HN_ + 255)/256, 256>>>(E);
    split_arr<<<(MC_*N_ + 255)/256, 256>>>(Km, Km_h, Km_l, MC_*N_);
    split_arr<<<(KF_*N_ + 255)/256, 256>>>(Estu, Es_h, Es_l, KF_*N_);
    transpose_split<<<dim3(N_/32, KF_/32), dim3(32, 8)>>>(Estu, EsT_h, EsT_l, KF_, N_);
    transpose_split<<<dim3(N_/32, N_/32),  dim3(32, 8)>>>(Q, Qt_h, Qt_l, N_, N_);
    transpose_split<<<dim3(MC_/32, MC_/32), dim3(32, 8)>>>(R, Rt_h, Rt_l, MC_, MC_);

    // ---- u_pert = WWs @ Ew^T + bias   (M=512,N=512,K=5120, z=16, 3-prod) ----
    gemm_mma<3><<<dim3(MC_/128, T_/128, 16), 256>>>(WWs_h, WWs_l, Ew_h, Ew_l, Cs, T_, MC_, HN_);
    reduce_epi<<<(T_*MC_ + 255)/256, 256>>>(Cs, P, bias, T_*MC_, MC_, 16, 1);

    // ---- Ft = Km @ Estu^T   (M=512,N=10240,K=1024, z=1, 1-prod) ----
    gemm_mma<1><<<dim3(KF_/128, MC_/128, 1), 256>>>(Km_h, Km_h, Es_h, Es_h, Cs, MC_, KF_, N_);
    split_arr<<<(MC_*KF_ + 255)/256, 256>>>(Cs, Ft_h, Ft_l, MC_*KF_);

    // ---- Neumann fixed-point: u <- p - L u ----
    copy_k<<<(T_*MC_ + 255)/256, 256>>>(P, U0, T_*MC_);
    float* ucur = U0; float* unext = U1;
    for (int it = 0; it < NITER; it++) {
        cumsum_u<<<dim3(MC_/128, NF_), 128>>>(ucur, phis);
        if (it < NITER - 1)
            gemm_mma<1><<<dim3(MC_/128, T_/128, 16), 256>>>(cb_h, cb_h, Ft_h, Ft_h, Cs, T_, MC_, KF_);
        else
            gemm_mma<3><<<dim3(MC_/128, T_/128, 16), 256>>>(cb_h, cb_l, Ft_h, Ft_l, Cs, T_, MC_, KF_);
        reduce_epi<<<(T_*MC_ + 255)/256, 256>>>(Cs, unext, P, T_*MC_, MC_, 16, 2);
        float* tmp = ucur; ucur = unext; unext = tmp;
    }

    // ---- X = cumsum(u) @ EstuT^T   (M=512,N=1024,K=10240, z=8, 3-prod) ----
    cumsum_u<<<dim3(MC_/128, NF_), 128>>>(ucur, phis);
    gemm_mma<3><<<dim3(N_/128, T_/128, 8), 256>>>(cb_h, cb_l, EsT_h, EsT_l, Cs, T_, N_, KF_);
    reduce_split<<<(T_*N_ + 255)/256, 256>>>(Cs, X, X_h, X_l, T_*N_, 8);

    // ---- QX = X @ Qt^T   (M=512,N=1024,K=1024, z=4, 3-prod) ----
    gemm_mma<3><<<dim3(N_/128, T_/128, 4), 256>>>(X_h, X_l, Qt_h, Qt_l, Cs, T_, N_, N_);
    reduce_epi<<<(T_*N_ + 255)/256, 256>>>(Cs, QX, nullptr, T_*N_, N_, 4, 0);

    // ---- RU = u @ Rt^T   (M=512,N=512,K=512, z=4, 3-prod) ----
    split_arr<<<(T_*MC_ + 255)/256, 256>>>(ucur, u_h, u_l, T_*MC_);
    gemm_mma<3><<<dim3(MC_/128, T_/128, 4), 256>>>(u_h, u_l, Rt_h, Rt_l, Cs, T_, MC_, MC_);
    reduce_epi<<<(T_*MC_ + 255)/256, 256>>>(Cs, RU, nullptr, T_*MC_, MC_, 4, 0);

    // ---- losses ----
    losses_k<<<T_, 256>>>(X, QX, ucur, RU, out);
}

// round 4
// speedup vs baseline: 3.1179x; 1.2200x over previous
#include <cuda_runtime.h>
#include <cuda_bf16.h>
#include <math.h>
#include <stdint.h>

#define T_   512
#define N_   1024
#define MC_  512
#define H_   5
#define MW_  20
#define NF_  20
#define KF_  (NF_*MC_)   // 10240
#define HN_  (H_*N_)     // 5120
#define NITER 3
#define NCH  8
#define CHL  (T_/NCH)    // 64

typedef __nv_bfloat16 bf16;

// ---------------- device scratch ----------------
__device__ bf16  g_WWs_h[(size_t)T_*HN_],  g_WWs_l[(size_t)T_*HN_];
__device__ bf16  g_Ew_h [(size_t)MC_*HN_], g_Ew_l [(size_t)MC_*HN_];
__device__ bf16  g_Km_h [(size_t)MC_*N_];
__device__ bf16  g_Es_h [(size_t)KF_*N_];                             // Estu flat (B of Ft, 1-prod)
__device__ bf16  g_EsT_h[(size_t)N_*KF_],  g_EsT_l[(size_t)N_*KF_];   // Estu^T (B of X, 3-prod)
__device__ bf16  g_Qt_h [(size_t)N_*N_],   g_Qt_l [(size_t)N_*N_];
__device__ bf16  g_Rt_h [(size_t)MC_*MC_], g_Rt_l [(size_t)MC_*MC_];
__device__ bf16  g_Ft_h [(size_t)MC_*KF_], g_Ft_l [(size_t)MC_*KF_];
__device__ bf16  g_cb_h [(size_t)T_*KF_],  g_cb_l [(size_t)T_*KF_];
__device__ bf16  g_X_h  [(size_t)T_*N_],   g_X_l  [(size_t)T_*N_];
__device__ bf16  g_u_h  [(size_t)T_*MC_],  g_u_l  [(size_t)T_*MC_];
__device__ float g_P   [(size_t)T_*MC_];
__device__ float g_u0  [(size_t)T_*MC_];
__device__ float g_u1  [(size_t)T_*MC_];
__device__ float g_X   [(size_t)T_*N_];
__device__ float g_QX  [(size_t)T_*N_];
__device__ float g_RU  [(size_t)T_*MC_];
__device__ float g_ctot[(size_t)NCH*KF_];
__device__ float g_Cs  [(size_t)T_*KF_];  // scan scratch / split-K slabs (5.24M floats)

__device__ __forceinline__ void split2(float x, bf16& h, bf16& l) {
    h = __float2bfloat16(x);
    l = __float2bfloat16(x - __bfloat162float(h));
}

// ---------------- producers ----------------

__global__ void build_WWs(const float* __restrict__ phi, const float* __restrict__ sigma,
                          const float* __restrict__ W)
{
    int t = blockIdx.x;
    for (int idx = threadIdx.x; idx < HN_; idx += blockDim.x) {
        int i = idx / N_, n = idx - i * N_;
        float s4 = sqrtf(sqrtf(sigma[i]));
        float sum = 0.f;
        #pragma unroll
        for (int k = 0; k < MW_; k++) {
            int src = t + k - (MW_ - 1);
            if (src >= 0) sum += phi[k*H_ + i] * W[(size_t)src*N_ + n];
        }
        split2(s4 * sum, g_WWs_h[(size_t)t*HN_ + idx], g_WWs_l[(size_t)t*HN_ + idx]);
    }
}

// Ew[c][i*N+n] = E[c,n,i]   (E is (MC,N,H) row-major)
__global__ void build_Ew(const float* __restrict__ E)
{
    int idx = blockIdx.x * blockDim.x + threadIdx.x;
    if (idx >= MC_ * HN_) return;
    int c = idx / HN_, k = idx - c * HN_;
    int i = k / N_, n = k - i * N_;
    split2(E[((size_t)c*N_ + n)*H_ + i], g_Ew_h[idx], g_Ew_l[idx]);
}

__global__ void conv_bf16(const float* __restrict__ in, bf16* __restrict__ oh, int n)
{
    int i = blockIdx.x * blockDim.x + threadIdx.x;
    if (i < n) oh[i] = __float2bfloat16(in[i]);
}

// one pass over Estu [KF, N]: emit Es_h (same layout, bf16) + EsT_h/l (transposed, split)
__global__ void prep_Estu(const float* __restrict__ in)
{
    __shared__ float tile[32][33];
    int c0 = blockIdx.x * 32, r0 = blockIdx.y * 32;
    for (int dy = threadIdx.y; dy < 32; dy += 8) {
        size_t src = (size_t)(r0 + dy)*N_ + c0 + threadIdx.x;
        float v = in[src];
        g_Es_h[src] = __float2bfloat16(v);
        tile[dy][threadIdx.x] = v;
    }
    __syncthreads();
    for (int dy = threadIdx.y; dy < 32; dy += 8) {
        size_t o = (size_t)(c0 + dy)*KF_ + r0 + threadIdx.x;
        split2(tile[threadIdx.x][dy], g_EsT_h[o], g_EsT_l[o]);
    }
}

// out[c][r] = split(in[r][c])
__global__ void transpose_split(const float* __restrict__ in, bf16* __restrict__ oh,
                                bf16* __restrict__ ol, int rows, int cols)
{
    __shared__ float tile[32][33];
    int c0 = blockIdx.x * 32, r0 = blockIdx.y * 32;
    for (int dy = threadIdx.y; dy < 32; dy += 8)
        tile[dy][threadIdx.x] = in[(size_t)(r0 + dy)*cols + c0 + threadIdx.x];
    __syncthreads();
    for (int dy = threadIdx.y; dy < 32; dy += 8) {
        size_t o = (size_t)(c0 + dy)*rows + r0 + threadIdx.x;
        split2(tile[threadIdx.x][dy], oh[o], ol[o]);
    }
}

// ---------------- chunked exclusive scan: cb[t][f*MC+c] = sum_{s<t} phis[s,f]*u[s,c] ----
__global__ void cumsum_p1(const float* __restrict__ u, const float* __restrict__ phis,
                          float* __restrict__ Cs)
{
    int f = blockIdx.y, ch = blockIdx.z;
    int c = blockIdx.x * 128 + threadIdx.x;
    int idx = f*MC_ + c;
    float acc = 0.f;
    int t0 = ch * CHL;
    #pragma unroll 4
    for (int i = 0; i < CHL; i++) {
        int t = t0 + i;
        Cs[(size_t)t*KF_ + idx] = acc;
        acc += phis[t*NF_ + f] * u[(size_t)t*MC_ + c];
    }
    g_ctot[(size_t)ch*KF_ + idx] = acc;
}

template<bool WANTLOW>
__global__ void cumsum_p2(const float* __restrict__ Cs)
{
    int f = blockIdx.y, ch = blockIdx.z;
    int c = blockIdx.x * 128 + threadIdx.x;
    int idx = f*MC_ + c;
    float off = 0.f;
    for (int j = 0; j < ch; j++) off += g_ctot[(size_t)j*KF_ + idx];
    int t0 = ch * CHL;
    #pragma unroll 4
    for (int i = 0; i < CHL; i++) {
        size_t o = (size_t)(t0 + i)*KF_ + idx;
        float v = Cs[o] + off;
        bf16 h = __float2bfloat16(v);
        g_cb_h[o] = h;
        if (WANTLOW) g_cb_l[o] = __float2bfloat16(v - __bfloat162float(h));
    }
}

// ---------------- mma.sync bf16 GEMM (2-stage ping-pong smem) ----------------
// C = A[M,K] * B^T, B stored [Nn,K] k-major. 128x128 CTA tile, BK=16, 256 thr
// (8 warps = 4m x 2n), warp tile 32x64, mma m16n8k16.
// EPI 0: f32 slab at blockIdx.z. EPI 1: split-bf16 direct (requires gridDim.z==1).

__device__ __forceinline__ void mma16816(float* c, const uint32_t* a, uint32_t b0, uint32_t b1)
{
    asm volatile(
        "mma.sync.aligned.m16n8k16.row.col.f32.bf16.bf16.f32 "
        "{%0,%1,%2,%3}, {%4,%5,%6,%7}, {%8,%9}, {%0,%1,%2,%3};"
        : "+f"(c[0]), "+f"(c[1]), "+f"(c[2]), "+f"(c[3])
        : "r"(a[0]), "r"(a[1]), "r"(a[2]), "r"(a[3]), "r"(b0), "r"(b1));
}

template<int NPROD, int EPI>
__global__ __launch_bounds__(256, 2) void gemm_mma(
    const bf16* __restrict__ Ah, const bf16* __restrict__ Al,
    const bf16* __restrict__ Bh, const bf16* __restrict__ Bl,
    float* __restrict__ C, bf16* __restrict__ Oh, bf16* __restrict__ Ol,
    int M, int Nn, int K)
{
    constexpr int NB = (NPROD == 3) ? 2 : 1;
    const int tid = threadIdx.x;
    const int wid = tid >> 5, lane = tid & 31;
    const int g = lane >> 2, tg = lane & 3;
    const int n0 = blockIdx.x * 128, m0 = blockIdx.y * 128;
    const int Ks = K / gridDim.z;
    const int kbeg = blockIdx.z * Ks;
    const int warp_m = (wid >> 1) * 32, warp_n = (wid & 1) * 64;

    __shared__ bf16 Ash[2][NB][128][24];
    __shared__ bf16 Bsh[2][NB][128][24];

    float acc[2][8][4];
    #pragma unroll
    for (int i = 0; i < 2; i++)
        #pragma unroll
        for (int j = 0; j < 8; j++)
            #pragma unroll
            for (int q = 0; q < 4; q++) acc[i][j][q] = 0.f;

    const int lrow = tid >> 1, lk = (tid & 1) * 8;
    const bf16* Aph = Ah + (size_t)(m0 + lrow)*K + kbeg + lk;
    const bf16* Bph = Bh + (size_t)(n0 + lrow)*K + kbeg + lk;
    const bf16* Apl = (NPROD == 3) ? Al + (size_t)(m0 + lrow)*K + kbeg + lk : Aph;
    const bf16* Bpl = (NPROD == 3) ? Bl + (size_t)(n0 + lrow)*K + kbeg + lk : Bph;

    uint4 sA0 = *(const uint4*)Aph;
    uint4 sB0 = *(const uint4*)Bph;
    uint4 sA1, sB1;
    if (NPROD == 3) { sA1 = *(const uint4*)Apl; sB1 = *(const uint4*)Bpl; }

    // stage 0 fill
    *(uint4*)&Ash[0][0][lrow][lk] = sA0;
    *(uint4*)&Bsh[0][0][lrow][lk] = sB0;
    if (NPROD == 3) {
        *(uint4*)&Ash[0][1][lrow][lk] = sA1;
        *(uint4*)&Bsh[0][1][lrow][lk] = sB1;
    }
    __syncthreads();

    int st = 0;
    for (int kt = 0; kt < Ks; kt += 16) {
        const bool hn = (kt + 16) < Ks;
        if (hn) {
            sA0 = *(const uint4*)(Aph + kt + 16);
            sB0 = *(const uint4*)(Bph + kt + 16);
            if (NPROD == 3) {
                sA1 = *(const uint4*)(Apl + kt + 16);
                sB1 = *(const uint4*)(Bpl + kt + 16);
            }
        }

        uint32_t ah[2][4], al[2][4];
        #pragma unroll
        for (int mt = 0; mt < 2; mt++) {
            int r = warp_m + mt*16 + g;
            ah[mt][0] = *(const uint32_t*)&Ash[st][0][r    ][2*tg    ];
            ah[mt][1] = *(const uint32_t*)&Ash[st][0][r + 8][2*tg    ];
            ah[mt][2] = *(const uint32_t*)&Ash[st][0][r    ][2*tg + 8];
            ah[mt][3] = *(const uint32_t*)&Ash[st][0][r + 8][2*tg + 8];
            if (NPROD == 3) {
                al[mt][0] = *(const uint32_t*)&Ash[st][NB-1][r    ][2*tg    ];
                al[mt][1] = *(const uint32_t*)&Ash[st][NB-1][r + 8][2*tg    ];
                al[mt][2] = *(const uint32_t*)&Ash[st][NB-1][r    ][2*tg + 8];
                al[mt][3] = *(const uint32_t*)&Ash[st][NB-1][r + 8][2*tg + 8];
            }
        }
        #pragma unroll
        for (int nt = 0; nt < 8; nt++) {
            int nr = warp_n + nt*8 + g;
            uint32_t bh0 = *(const uint32_t*)&Bsh[st][0][nr][2*tg    ];
            uint32_t bh1 = *(const uint32_t*)&Bsh[st][0][nr][2*tg + 8];
            #pragma unroll
            for (int mt = 0; mt < 2; mt++)
                mma16816(acc[mt][nt], ah[mt], bh0, bh1);
            if (NPROD == 3) {
                uint32_t bl0 = *(const uint32_t*)&Bsh[st][NB-1][nr][2*tg    ];
                uint32_t bl1 = *(const uint32_t*)&Bsh[st][NB-1][nr][2*tg + 8];
                #pragma unroll
                for (int mt = 0; mt < 2; mt++) {
                    mma16816(acc[mt][nt], ah[mt], bl0, bl1);
                    mma16816(acc[mt][nt], al[mt], bh0, bh1);
                }
            }
        }

        if (hn) {
            st ^= 1;
            *(uint4*)&Ash[st][0][lrow][lk] = sA0;
            *(uint4*)&Bsh[st][0][lrow][lk] = sB0;
            if (NPROD == 3) {
                *(uint4*)&Ash[st][NB-1][lrow][lk] = sA1;
                *(uint4*)&Bsh[st][NB-1][lrow][lk] = sB1;
            }
            __syncthreads();
        }
    }

    #pragma unroll
    for (int mt = 0; mt < 2; mt++) {
        #pragma unroll
        for (int nt = 0; nt < 8; nt++) {
            int row = m0 + warp_m + mt*16 + g;
            int col = n0 + warp_n + nt*8 + 2*tg;
            if (EPI == 0) {
                float* Cb = C + (size_t)blockIdx.z * M * Nn;
                *(float2*)&Cb[(size_t)row*Nn + col]     = make_float2(acc[mt][nt][0], acc[mt][nt][1]);
                *(float2*)&Cb[(size_t)(row+8)*Nn + col] = make_float2(acc[mt][nt][2], acc[mt][nt][3]);
            } else {
                #pragma unroll
                for (int rr = 0; rr < 2; rr++) {
                    size_t o = (size_t)(row + 8*rr)*Nn + col;
                    split2(acc[mt][nt][2*rr    ], Oh[o],     Ol[o]);
                    split2(acc[mt][nt][2*rr + 1], Oh[o + 1], Ol[o + 1]);
                }
            }
        }
    }
}

// ---------------- reductions / epilogues ----------------
// mode 0: out=sum ; 1: out=sum+extra[i%Nn] ; 2: out=extra[i]-sum
__global__ void reduce_epi(const float* __restrict__ Cs, float* __restrict__ out,
                           const float* __restrict__ extra, int MN, int Nn, int S, int mode)
{
    int i = blockIdx.x * blockDim.x + threadIdx.x;
    if (i >= MN) return;
    float s = 0.f;
    for (int z = 0; z < S; z++) s += Cs[(size_t)z*MN + i];
    if (mode == 0)      out[i] = s;
    else if (mode == 1) out[i] = s + extra[i % Nn];
    else                out[i] = extra[i] - s;
}

// final Neumann reduce: u = P - sum, also emit split bf16 of u
__global__ void reduce_final(const float* __restrict__ Cs, const float* __restrict__ P,
                             float* __restrict__ out, bf16* __restrict__ oh,
                             bf16* __restrict__ ol, int MN, int S)
{
    int i = blockIdx.x * blockDim.x + threadIdx.x;
    if (i >= MN) return;
    float s = 0.f;
    for (int z = 0; z < S; z++) s += Cs[(size_t)z*MN + i];
    float v = P[i] - s;
    out[i] = v;
    split2(v, oh[i], ol[i]);
}

// sum slabs -> f32 + split bf16 (for X)
__global__ void reduce_split(const float* __restrict__ Cs, float* __restrict__ out,
                             bf16* __restrict__ oh, bf16* __restrict__ ol, int MN, int S)
{
    int i = blockIdx.x * blockDim.x + threadIdx.x;
    if (i >= MN) return;
    float s = 0.f;
    for (int z = 0; z < S; z++) s += Cs[(size_t)z*MN + i];
    out[i] = s;
    split2(s, oh[i], ol[i]);
}

__global__ void losses_k(const float* __restrict__ X, const float* __restrict__ QX,
                         const float* __restrict__ U, const float* __restrict__ RU,
                         float* __restrict__ out)
{
    int t = blockIdx.x;
    float s = 0.f;
    for (int n = threadIdx.x; n < N_;  n += 256) s += X[(size_t)t*N_ + n] * QX[(size_t)t*N_ + n];
    for (int c = threadIdx.x; c < MC_; c += 256) s += U[(size_t)t*MC_ + c] * RU[(size_t)t*MC_ + c];
    __shared__ float red[256];
    red[threadIdx.x] = s;
    __syncthreads();
    for (int o = 128; o > 0; o >>= 1) {
        if (threadIdx.x < o) red[threadIdx.x] += red[threadIdx.x + o];
        __syncthreads();
    }
    if (threadIdx.x == 0) out[t] = red[0];
}

// ---------------- host ----------------

template<typename Tp> static Tp* sym(const void* s) { void* p; cudaGetSymbolAddress(&p, s); return (Tp*)p; }

extern "C" void kernel_launch(void* const* d_in, const int* in_sizes, int n_in,
                              void* d_out, int out_size)
{
    (void)in_sizes; (void)n_in; (void)out_size;
    const float* Q    = (const float*)d_in[0];
    const float* R    = (const float*)d_in[1];
    const float* Km   = (const float*)d_in[2];
    const float* E    = (const float*)d_in[3];
    const float* bias = (const float*)d_in[4];
    const float* Estu = (const float*)d_in[5];
    const float* phi  = (const float*)d_in[6];
    const float* sig  = (const float*)d_in[7];
    const float* phis = (const float*)d_in[8];
    const float* W    = (const float*)d_in[9];
    float* out = (float*)d_out;

    bf16 *WWs_h = sym<bf16>(g_WWs_h), *WWs_l = sym<bf16>(g_WWs_l);
    bf16 *Ew_h  = sym<bf16>(g_Ew_h),  *Ew_l  = sym<bf16>(g_Ew_l);
    bf16 *Km_h  = sym<bf16>(g_Km_h);
    bf16 *Es_h  = sym<bf16>(g_Es_h);
    bf16 *EsT_h = sym<bf16>(g_EsT_h), *EsT_l = sym<bf16>(g_EsT_l);
    bf16 *Qt_h  = sym<bf16>(g_Qt_h),  *Qt_l  = sym<bf16>(g_Qt_l);
    bf16 *Rt_h  = sym<bf16>(g_Rt_h),  *Rt_l  = sym<bf16>(g_Rt_l);
    bf16 *Ft_h  = sym<bf16>(g_Ft_h),  *Ft_l  = sym<bf16>(g_Ft_l);
    bf16 *cb_h  = sym<bf16>(g_cb_h),  *cb_l  = sym<bf16>(g_cb_l);
    bf16 *X_h   = sym<bf16>(g_X_h),   *X_l   = sym<bf16>(g_X_l);
    bf16 *u_h   = sym<bf16>(g_u_h),   *u_l   = sym<bf16>(g_u_l);
    float *P  = sym<float>(g_P),  *U0 = sym<float>(g_u0), *U1 = sym<float>(g_u1);
    float *X  = sym<float>(g_X),  *QX = sym<float>(g_QX), *RU = sym<float>(g_RU);
    float *Cs = sym<float>(g_Cs);

    // ---- one-time operand prep ----
    build_WWs<<<T_, 256>>>(phi, sig, W);
    build_Ew<<<(MC_*HN_ + 255)/256, 256>>>(E);
    conv_bf16<<<(MC_*N_ + 255)/256, 256>>>(Km, Km_h, MC_*N_);
    prep_Estu<<<dim3(N_/32, KF_/32), dim3(32, 8)>>>(Estu);
    transpose_split<<<dim3(N_/32, N_/32),   dim3(32, 8)>>>(Q, Qt_h, Qt_l, N_, N_);
    transpose_split<<<dim3(MC_/32, MC_/32), dim3(32, 8)>>>(R, Rt_h, Rt_l, MC_, MC_);

    // ---- u_pert = WWs @ Ew^T + bias   (z=16, 3-prod) ----
    gemm_mma<3,0><<<dim3(MC_/128, T_/128, 16), 256>>>(WWs_h, WWs_l, Ew_h, Ew_l,
                                                      Cs, nullptr, nullptr, T_, MC_, HN_);
    reduce_epi<<<(T_*MC_ + 255)/256, 256>>>(Cs, P, bias, T_*MC_, MC_, 16, 1);

    // ---- Ft = Km @ Estu^T, split-bf16 epilogue (z=1, 1-prod) ----
    gemm_mma<1,1><<<dim3(KF_/128, MC_/128, 1), 256>>>(Km_h, Km_h, Es_h, Es_h,
                                                      nullptr, Ft_h, Ft_l, MC_, KF_, N_);

    // ---- Neumann fixed-point (3 iters): u <- p - L u ----
    const float* ucur = P;
    float* bufs[2] = { U0, U1 };
    for (int it = 0; it < NITER; it++) {
        cumsum_p1<<<dim3(MC_/128, NF_, NCH), 128>>>(ucur, phis, Cs);
        if (it < NITER - 1) {
            cumsum_p2<false><<<dim3(MC_/128, NF_, NCH), 128>>>(Cs);
            gemm_mma<1,0><<<dim3(MC_/128, T_/128, 16), 256>>>(cb_h, cb_h, Ft_h, Ft_h,
                                                              Cs, nullptr, nullptr, T_, MC_, KF_);
            reduce_epi<<<(T_*MC_ + 255)/256, 256>>>(Cs, bufs[it & 1], P, T_*MC_, MC_, 16, 2);
        } else {
            cumsum_p2<true><<<dim3(MC_/128, NF_, NCH), 128>>>(Cs);
            gemm_mma<3,0><<<dim3(MC_/128, T_/128, 16), 256>>>(cb_h, cb_l, Ft_h, Ft_l,
                                                              Cs, nullptr, nullptr, T_, MC_, KF_);
            reduce_final<<<(T_*MC_ + 255)/256, 256>>>(Cs, P, bufs[it & 1], u_h, u_l, T_*MC_, 16);
        }
        ucur = bufs[it & 1];
    }
    float* ufin = bufs[(NITER - 1) & 1];

    // ---- X = cumsum(u) @ EstuT^T   (z=8, 3-prod) ----
    cumsum_p1<<<dim3(MC_/128, NF_, NCH), 128>>>(ufin, phis, Cs);
    cumsum_p2<true><<<dim3(MC_/128, NF_, NCH), 128>>>(Cs);
    gemm_mma<3,0><<<dim3(N_/128, T_/128, 8), 256>>>(cb_h, cb_l, EsT_h, EsT_l,
                                                    Cs, nullptr, nullptr, T_, N_, KF_);
    reduce_split<<<(T_*N_ + 255)/256, 256>>>(Cs, X, X_h, X_l, T_*N_, 8);

    // ---- QX = X @ Qt^T   (z=8, 3-prod) ----
    gemm_mma<3,0><<<dim3(N_/128, T_/128, 8), 256>>>(X_h, X_l, Qt_h, Qt_l,
                                                    Cs, nullptr, nullptr, T_, N_, N_);
    reduce_epi<<<(T_*N_ + 255)/256, 256>>>(Cs, QX, nullptr, T_*N_, N_, 8, 0);

    // ---- RU = u @ Rt^T   (z=16, 3-prod) ----
    gemm_mma<3,0><<<dim3(MC_/128, T_/128, 16), 256>>>(u_h, u_l, Rt_h, Rt_l,
                                                      Cs, nullptr, nullptr, T_, MC_, MC_);
    reduce_epi<<<(T_*MC_ + 255)/256, 256>>>(Cs, RU, nullptr, T_*MC_, MC_, 16, 0);

    // ---- losses ----
    losses_k<<<T_, 256>>>(X, QX, ufin, RU, out);
}

// round 5
// speedup vs baseline: 3.1880x; 1.0225x over previous
#include <cuda_runtime.h>
#include <cuda_bf16.h>
#include <math.h>
#include <stdint.h>

#define T_   512
#define N_   1024
#define MC_  512
#define H_   5
#define MW_  20
#define NF_  20
#define KF_  (NF_*MC_)   // 10240
#define HN_  (H_*N_)     // 5120
#define HM_  (H_*MC_)    // 2560
#define NITER 2
#define NCH  8
#define CHL  (T_/NCH)    // 64

typedef __nv_bfloat16 bf16;

// ---------------- device scratch ----------------
__device__ bf16  g_Wh  [(size_t)T_*N_],    g_Wl  [(size_t)T_*N_];
__device__ bf16  g_Gh  [(size_t)HM_*N_],   g_Gl  [(size_t)HM_*N_];   // G[i*MC+c][n]=E[c,n,i]
__device__ bf16  g_Km_h [(size_t)MC_*N_];
__device__ bf16  g_Es_h [(size_t)KF_*N_];                             // Estu flat (B of Ft)
__device__ bf16  g_EsT_h[(size_t)N_*KF_],  g_EsT_l[(size_t)N_*KF_];   // Estu^T (B of X)
__device__ bf16  g_Qt_h [(size_t)N_*N_],   g_Qt_l [(size_t)N_*N_];
__device__ bf16  g_Rt_h [(size_t)MC_*MC_], g_Rt_l [(size_t)MC_*MC_];
__device__ bf16  g_Ft_h [(size_t)MC_*KF_], g_Ft_l [(size_t)MC_*KF_];
__device__ bf16  g_cb_h [(size_t)T_*KF_],  g_cb_l [(size_t)T_*KF_];
__device__ bf16  g_X_h  [(size_t)T_*N_],   g_X_l  [(size_t)T_*N_];
__device__ bf16  g_u_h  [(size_t)T_*MC_],  g_u_l  [(size_t)T_*MC_];
__device__ float g_V   [(size_t)T_*HM_];   // V[t][i*MC+c]
__device__ float g_P   [(size_t)T_*MC_];
__device__ float g_u0  [(size_t)T_*MC_];
__device__ float g_u1  [(size_t)T_*MC_];
__device__ float g_X   [(size_t)T_*N_];
__device__ float g_QX  [(size_t)T_*N_];
__device__ float g_RU  [(size_t)T_*MC_];
__device__ float g_ctot[(size_t)NCH*KF_];
__device__ float g_Cs  [(size_t)T_*KF_];  // split-K slabs (5.24M floats)

__device__ __forceinline__ void split2(float x, bf16& h, bf16& l) {
    h = __float2bfloat16(x);
    l = __float2bfloat16(x - __bfloat162float(h));
}

// ---------------- producers ----------------

__global__ void split_arr(const float* __restrict__ in, bf16* __restrict__ oh,
                          bf16* __restrict__ ol, int n)
{
    int i = blockIdx.x * blockDim.x + threadIdx.x;
    if (i < n) split2(in[i], oh[i], ol[i]);
}

__global__ void conv_only(const float* __restrict__ in, bf16* __restrict__ oh, int n)
{
    int i = blockIdx.x * blockDim.x + threadIdx.x;
    if (i < n) oh[i] = __float2bfloat16(in[i]);
}

// G[(i*MC+c)][n] = E[c,n,i]   (E is (MC,N,H) row-major)
__global__ void build_G(const float* __restrict__ E)
{
    int idx = blockIdx.x * blockDim.x + threadIdx.x;
    if (idx >= HM_ * N_) return;
    int r = idx / N_, n = idx - r * N_;
    int i = r / MC_, c = r - i * MC_;
    split2(E[((size_t)c*N_ + n)*H_ + i], g_Gh[idx], g_Gl[idx]);
}

// one pass over Estu [KF, N]: emit Es_h (same layout, bf16) + EsT_h/l (transposed, split)
__global__ void prep_Estu(const float* __restrict__ in)
{
    __shared__ float tile[32][33];
    int c0 = blockIdx.x * 32, r0 = blockIdx.y * 32;
    for (int dy = threadIdx.y; dy < 32; dy += 8) {
        size_t src = (size_t)(r0 + dy)*N_ + c0 + threadIdx.x;
        float v = in[src];
        g_Es_h[src] = __float2bfloat16(v);
        tile[dy][threadIdx.x] = v;
    }
    __syncthreads();
    for (int dy = threadIdx.y; dy < 32; dy += 8) {
        size_t o = (size_t)(c0 + dy)*KF_ + r0 + threadIdx.x;
        split2(tile[threadIdx.x][dy], g_EsT_h[o], g_EsT_l[o]);
    }
}

// out[c][r] = split(in[r][c])
__global__ void transpose_split(const float* __restrict__ in, bf16* __restrict__ oh,
                                bf16* __restrict__ ol, int rows, int cols)
{
    __shared__ float tile[32][33];
    int c0 = blockIdx.x * 32, r0 = blockIdx.y * 32;
    for (int dy = threadIdx.y; dy < 32; dy += 8)
        tile[dy][threadIdx.x] = in[(size_t)(r0 + dy)*cols + c0 + threadIdx.x];
    __syncthreads();
    for (int dy = threadIdx.y; dy < 32; dy += 8) {
        size_t o = (size_t)(c0 + dy)*rows + r0 + threadIdx.x;
        split2(tile[threadIdx.x][dy], oh[o], ol[o]);
    }
}

// u_pert[t,c] = bias[c] + sum_{i,k} phi[k,i]*sig_i^.25 * V[t+k-(MW-1)][i*MC+c]
__global__ void conv_upert(const float* __restrict__ phi, const float* __restrict__ sig,
                           const float* __restrict__ bias, const float* __restrict__ V,
                           float* __restrict__ P)
{
    __shared__ float w[MW_*H_];
    if (threadIdx.x < MW_*H_) {
        int i = threadIdx.x % H_;
        w[threadIdx.x] = phi[threadIdx.x] * sqrtf(sqrtf(sig[i]));
    }
    __syncthreads();
    int c = blockIdx.x * 128 + threadIdx.x;
    float b = bias[c];
    int t0 = blockIdx.y * CHL;
    for (int t = t0; t < t0 + CHL; t++) {
        float s = b;
        #pragma unroll
        for (int k = 0; k < MW_; k++) {
            int tp = t + k - (MW_ - 1);
            if (tp >= 0) {
                const float* Vr = V + (size_t)tp*HM_ + c;
                #pragma unroll
                for (int i = 0; i < H_; i++)
                    s += w[k*H_ + i] * Vr[i*MC_];
            }
        }
        P[(size_t)t*MC_ + c] = s;
    }
}

// ---------------- fused chunked exclusive scan ----------------
// k1: chunk totals only. k2: recompute scan from u, write bf16 directly.
__global__ void csum_tot(const float* __restrict__ u, const float* __restrict__ phis)
{
    int f = blockIdx.y, ch = blockIdx.z;
    int c = blockIdx.x * 128 + threadIdx.x;
    int t0 = ch * CHL;
    float acc = 0.f;
    #pragma unroll 4
    for (int i = 0; i < CHL; i++) {
        int t = t0 + i;
        acc += phis[t*NF_ + f] * u[(size_t)t*MC_ + c];
    }
    g_ctot[(size_t)ch*KF_ + f*MC_ + c] = acc;
}

template<bool WANTLOW>
__global__ void csum_scan(const float* __restrict__ u, const float* __restrict__ phis)
{
    int f = blockIdx.y, ch = blockIdx.z;
    int c = blockIdx.x * 128 + threadIdx.x;
    int idx = f*MC_ + c;
    float acc = 0.f;
    for (int j = 0; j < ch; j++) acc += g_ctot[(size_t)j*KF_ + idx];
    int t0 = ch * CHL;
    #pragma unroll 4
    for (int i = 0; i < CHL; i++) {
        int t = t0 + i;
        size_t o = (size_t)t*KF_ + idx;
        bf16 h = __float2bfloat16(acc);
        g_cb_h[o] = h;
        if (WANTLOW) g_cb_l[o] = __float2bfloat16(acc - __bfloat162float(h));
        acc += phis[t*NF_ + f] * u[(size_t)t*MC_ + c];
    }
}

// ---------------- mma.sync bf16 GEMM (2-stage ping-pong smem) ----------------
// C = A[M,K] * B^T, B stored [Nn,K] k-major. 128x128 CTA tile, BK=16, 256 thr
// (8 warps = 4m x 2n), warp tile 32x64, mma m16n8k16.
// EPI 0: f32 slab at blockIdx.z. EPI 1: split-bf16 direct (requires gridDim.z==1).

__device__ __forceinline__ void mma16816(float* c, const uint32_t* a, uint32_t b0, uint32_t b1)
{
    asm volatile(
        "mma.sync.aligned.m16n8k16.row.col.f32.bf16.bf16.f32 "
        "{%0,%1,%2,%3}, {%4,%5,%6,%7}, {%8,%9}, {%0,%1,%2,%3};"
        : "+f"(c[0]), "+f"(c[1]), "+f"(c[2]), "+f"(c[3])
        : "r"(a[0]), "r"(a[1]), "r"(a[2]), "r"(a[3]), "r"(b0), "r"(b1));
}

template<int NPROD, int EPI>
__global__ __launch_bounds__(256, 2) void gemm_mma(
    const bf16* __restrict__ Ah, const bf16* __restrict__ Al,
    const bf16* __restrict__ Bh, const bf16* __restrict__ Bl,
    float* __restrict__ C, bf16* __restrict__ Oh, bf16* __restrict__ Ol,
    int M, int Nn, int K)
{
    constexpr int NB = (NPROD == 3) ? 2 : 1;
    const int tid = threadIdx.x;
    const int wid = tid >> 5, lane = tid & 31;
    const int g = lane >> 2, tg = lane & 3;
    const int n0 = blockIdx.x * 128, m0 = blockIdx.y * 128;
    const int Ks = K / gridDim.z;
    const int kbeg = blockIdx.z * Ks;
    const int warp_m = (wid >> 1) * 32, warp_n = (wid & 1) * 64;

    __shared__ bf16 Ash[2][NB][128][24];
    __shared__ bf16 Bsh[2][NB][128][24];

    float acc[2][8][4];
    #pragma unroll
    for (int i = 0; i < 2; i++)
        #pragma unroll
        for (int j = 0; j < 8; j++)
            #pragma unroll
            for (int q = 0; q < 4; q++) acc[i][j][q] = 0.f;

    const int lrow = tid >> 1, lk = (tid & 1) * 8;
    const bf16* Aph = Ah + (size_t)(m0 + lrow)*K + kbeg + lk;
    const bf16* Bph = Bh + (size_t)(n0 + lrow)*K + kbeg + lk;
    const bf16* Apl = (NPROD == 3) ? Al + (size_t)(m0 + lrow)*K + kbeg + lk : Aph;
    const bf16* Bpl = (NPROD == 3) ? Bl + (size_t)(n0 + lrow)*K + kbeg + lk : Bph;

    uint4 sA0 = *(const uint4*)Aph;
    uint4 sB0 = *(const uint4*)Bph;
    uint4 sA1, sB1;
    if (NPROD == 3) { sA1 = *(const uint4*)Apl; sB1 = *(const uint4*)Bpl; }

    *(uint4*)&Ash[0][0][lrow][lk] = sA0;
    *(uint4*)&Bsh[0][0][lrow][lk] = sB0;
    if (NPROD == 3) {
        *(uint4*)&Ash[0][1][lrow][lk] = sA1;
        *(uint4*)&Bsh[0][1][lrow][lk] = sB1;
    }
    __syncthreads();

    int st = 0;
    for (int kt = 0; kt < Ks; kt += 16) {
        const bool hn = (kt + 16) < Ks;
        if (hn) {
            sA0 = *(const uint4*)(Aph + kt + 16);
            sB0 = *(const uint4*)(Bph + kt + 16);
            if (NPROD == 3) {
                sA1 = *(const uint4*)(Apl + kt + 16);
                sB1 = *(const uint4*)(Bpl + kt + 16);
            }
        }

        uint32_t ah[2][4], al[2][4];
        #pragma unroll
        for (int mt = 0; mt < 2; mt++) {
            int r = warp_m + mt*16 + g;
            ah[mt][0] = *(const uint32_t*)&Ash[st][0][r    ][2*tg    ];
            ah[mt][1] = *(const uint32_t*)&Ash[st][0][r + 8][2*tg    ];
            ah[mt][2] = *(const uint32_t*)&Ash[st][0][r    ][2*tg + 8];
            ah[mt][3] = *(const uint32_t*)&Ash[st][0][r + 8][2*tg + 8];
            if (NPROD == 3) {
                al[mt][0] = *(const uint32_t*)&Ash[st][NB-1][r    ][2*tg    ];
                al[mt][1] = *(const uint32_t*)&Ash[st][NB-1][r + 8][2*tg    ];
                al[mt][2] = *(const uint32_t*)&Ash[st][NB-1][r    ][2*tg + 8];
                al[mt][3] = *(const uint32_t*)&Ash[st][NB-1][r + 8][2*tg + 8];
            }
        }
        #pragma unroll
        for (int nt = 0; nt < 8; nt++) {
            int nr = warp_n + nt*8 + g;
            uint32_t bh0 = *(const uint32_t*)&Bsh[st][0][nr][2*tg    ];
            uint32_t bh1 = *(const uint32_t*)&Bsh[st][0][nr][2*tg + 8];
            #pragma unroll
            for (int mt = 0; mt < 2; mt++)
                mma16816(acc[mt][nt], ah[mt], bh0, bh1);
            if (NPROD == 3) {
                uint32_t bl0 = *(const uint32_t*)&Bsh[st][NB-1][nr][2*tg    ];
                uint32_t bl1 = *(const uint32_t*)&Bsh[st][NB-1][nr][2*tg + 8];
                #pragma unroll
                for (int mt = 0; mt < 2; mt++) {
                    mma16816(acc[mt][nt], ah[mt], bl0, bl1);
                    mma16816(acc[mt][nt], al[mt], bh0, bh1);
                }
            }
        }

        if (hn) {
            st ^= 1;
            *(uint4*)&Ash[st][0][lrow][lk] = sA0;
            *(uint4*)&Bsh[st][0][lrow][lk] = sB0;
            if (NPROD == 3) {
                *(uint4*)&Ash[st][NB-1][lrow][lk] = sA1;
                *(uint4*)&Bsh[st][NB-1][lrow][lk] = sB1;
            }
            __syncthreads();
        }
    }

    #pragma unroll
    for (int mt = 0; mt < 2; mt++) {
        #pragma unroll
        for (int nt = 0; nt < 8; nt++) {
            int row = m0 + warp_m + mt*16 + g;
            int col = n0 + warp_n + nt*8 + 2*tg;
            if (EPI == 0) {
                float* Cb = C + (size_t)blockIdx.z * M * Nn;
                *(float2*)&Cb[(size_t)row*Nn + col]     = make_float2(acc[mt][nt][0], acc[mt][nt][1]);
                *(float2*)&Cb[(size_t)(row+8)*Nn + col] = make_float2(acc[mt][nt][2], acc[mt][nt][3]);
            } else {
                #pragma unroll
                for (int rr = 0; rr < 2; rr++) {
                    size_t o = (size_t)(row + 8*rr)*Nn + col;
                    split2(acc[mt][nt][2*rr    ], Oh[o],     Ol[o]);
                    split2(acc[mt][nt][2*rr + 1], Oh[o + 1], Ol[o + 1]);
                }
            }
        }
    }
}

// ---------------- reductions / epilogues ----------------
// mode 0: out=sum ; 2: out=extra[i]-sum
__global__ void reduce_epi(const float* __restrict__ Cs, float* __restrict__ out,
                           const float* __restrict__ extra, int MN, int S, int mode)
{
    int i = blockIdx.x * blockDim.x + threadIdx.x;
    if (i >= MN) return;
    float s = 0.f;
    for (int z = 0; z < S; z++) s += Cs[(size_t)z*MN + i];
    if (mode == 0) out[i] = s;
    else           out[i] = extra[i] - s;
}

// final Neumann reduce: u = P - sum, also emit split bf16 of u
__global__ void reduce_final(const float* __restrict__ Cs, const float* __restrict__ P,
                             float* __restrict__ out, bf16* __restrict__ oh,
                             bf16* __restrict__ ol, int MN, int S)
{
    int i = blockIdx.x * blockDim.x + threadIdx.x;
    if (i >= MN) return;
    float s = 0.f;
    for (int z = 0; z < S; z++) s += Cs[(size_t)z*MN + i];
    float v = P[i] - s;
    out[i] = v;
    split2(v, oh[i], ol[i]);
}

// sum slabs -> f32 + split bf16 (for X)
__global__ void reduce_split(const float* __restrict__ Cs, float* __restrict__ out,
                             bf16* __restrict__ oh, bf16* __restrict__ ol, int MN, int S)
{
    int i = blockIdx.x * blockDim.x + threadIdx.x;
    if (i >= MN) return;
    float s = 0.f;
    for (int z = 0; z < S; z++) s += Cs[(size_t)z*MN + i];
    out[i] = s;
    split2(s, oh[i], ol[i]);
}

__global__ void losses_k(const float* __restrict__ X, const float* __restrict__ QX,
                         const float* __restrict__ U, const float* __restrict__ RU,
                         float* __restrict__ out)
{
    int t = blockIdx.x;
    float s = 0.f;
    for (int n = threadIdx.x; n < N_;  n += 256) s += X[(size_t)t*N_ + n] * QX[(size_t)t*N_ + n];
    for (int c = threadIdx.x; c < MC_; c += 256) s += U[(size_t)t*MC_ + c] * RU[(size_t)t*MC_ + c];
    __shared__ float red[256];
    red[threadIdx.x] = s;
    __syncthreads();
    for (int o = 128; o > 0; o >>= 1) {
        if (threadIdx.x < o) red[threadIdx.x] += red[threadIdx.x + o];
        __syncthreads();
    }
    if (threadIdx.x == 0) out[t] = red[0];
}

// ---------------- host ----------------

template<typename Tp> static Tp* sym(const void* s) { void* p; cudaGetSymbolAddress(&p, s); return (Tp*)p; }

extern "C" void kernel_launch(void* const* d_in, const int* in_sizes, int n_in,
                              void* d_out, int out_size)
{
    (void)in_sizes; (void)n_in; (void)out_size;
    const float* Q    = (const float*)d_in[0];
    const float* R    = (const float*)d_in[1];
    const float* Km   = (const float*)d_in[2];
    const float* E    = (const float*)d_in[3];
    const float* bias = (const float*)d_in[4];
    const float* Estu = (const float*)d_in[5];
    const float* phi  = (const float*)d_in[6];
    const float* sig  = (const float*)d_in[7];
    const float* phis = (const float*)d_in[8];
    const float* W    = (const float*)d_in[9];
    float* out = (float*)d_out;

    bf16 *Wh   = sym<bf16>(g_Wh),   *Wl   = sym<bf16>(g_Wl);
    bf16 *Gh   = sym<bf16>(g_Gh),   *Gl   = sym<bf16>(g_Gl);
    bf16 *Km_h = sym<bf16>(g_Km_h);
    bf16 *Es_h = sym<bf16>(g_Es_h);
    bf16 *EsT_h = sym<bf16>(g_EsT_h), *EsT_l = sym<bf16>(g_EsT_l);
    bf16 *Qt_h  = sym<bf16>(g_Qt_h),  *Qt_l  = sym<bf16>(g_Qt_l);
    bf16 *Rt_h  = sym<bf16>(g_Rt_h),  *Rt_l  = sym<bf16>(g_Rt_l);
    bf16 *Ft_h  = sym<bf16>(g_Ft_h),  *Ft_l  = sym<bf16>(g_Ft_l);
    bf16 *cb_h  = sym<bf16>(g_cb_h),  *cb_l  = sym<bf16>(g_cb_l);
    bf16 *X_h   = sym<bf16>(g_X_h),   *X_l   = sym<bf16>(g_X_l);
    bf16 *u_h   = sym<bf16>(g_u_h),   *u_l   = sym<bf16>(g_u_l);
    float *V  = sym<float>(g_V);
    float *P  = sym<float>(g_P),  *U0 = sym<float>(g_u0), *U1 = sym<float>(g_u1);
    float *X  = sym<float>(g_X),  *QX = sym<float>(g_QX), *RU = sym<float>(g_RU);
    float *Cs = sym<float>(g_Cs);

    // ---- one-time operand prep ----
    split_arr<<<(T_*N_ + 255)/256, 256>>>(W, Wh, Wl, T_*N_);
    build_G<<<(HM_*N_ + 255)/256, 256>>>(E);
    conv_only<<<(MC_*N_ + 255)/256, 256>>>(Km, Km_h, MC_*N_);
    prep_Estu<<<dim3(N_/32, KF_/32), dim3(32, 8)>>>(Estu);
    transpose_split<<<dim3(N_/32, N_/32),   dim3(32, 8)>>>(Q, Qt_h, Qt_l, N_, N_);
    transpose_split<<<dim3(MC_/32, MC_/32), dim3(32, 8)>>>(R, Rt_h, Rt_l, MC_, MC_);

    // ---- V = W @ G^T   [T x HM], z=2, 3-prod ----
    gemm_mma<3,0><<<dim3(HM_/128, T_/128, 2), 256>>>(Wh, Wl, Gh, Gl,
                                                     Cs, nullptr, nullptr, T_, HM_, N_);
    reduce_epi<<<(T_*HM_ + 255)/256, 256>>>(Cs, V, nullptr, T_*HM_, 2, 0);

    // ---- u_pert via small temporal conv over V ----
    conv_upert<<<dim3(MC_/128, NCH), 128>>>(phi, sig, bias, V, P);

    // ---- Ft = Km @ Estu^T, split-bf16 epilogue (z=1, 1-prod) ----
    gemm_mma<1,1><<<dim3(KF_/128, MC_/128, 1), 256>>>(Km_h, Km_h, Es_h, Es_h,
                                                      nullptr, Ft_h, Ft_l, MC_, KF_, N_);

    // ---- Neumann fixed-point (2 iters): u <- p - L u ----
    // it 0: 1-prod
    csum_tot<<<dim3(MC_/128, NF_, NCH), 128>>>(P, phis);
    csum_scan<false><<<dim3(MC_/128, NF_, NCH), 128>>>(P, phis);
    gemm_mma<1,0><<<dim3(MC_/128, T_/128, 16), 256>>>(cb_h, cb_h, Ft_h, Ft_h,
                                                      Cs, nullptr, nullptr, T_, MC_, KF_);
    reduce_epi<<<(T_*MC_ + 255)/256, 256>>>(Cs, U0, P, T_*MC_, 16, 2);
    // it 1: 3-prod, final
    csum_tot<<<dim3(MC_/128, NF_, NCH), 128>>>(U0, phis);
    csum_scan<true><<<dim3(MC_/128, NF_, NCH), 128>>>(U0, phis);
    gemm_mma<3,0><<<dim3(MC_/128, T_/128, 16), 256>>>(cb_h, cb_l, Ft_h, Ft_l,
                                                      Cs, nullptr, nullptr, T_, MC_, KF_);
    reduce_final<<<(T_*MC_ + 255)/256, 256>>>(Cs, P, U1, u_h, u_l, T_*MC_, 16);
    float* ufin = U1;

    // ---- X = cumsum(u) @ EstuT^T   (z=8, 3-prod) ----
    csum_tot<<<dim3(MC_/128, NF_, NCH), 128>>>(ufin, phis);
    csum_scan<true><<<dim3(MC_/128, NF_, NCH), 128>>>(ufin, phis);
    gemm_mma<3,0><<<dim3(N_/128, T_/128, 8), 256>>>(cb_h, cb_l, EsT_h, EsT_l,
                                                    Cs, nullptr, nullptr, T_, N_, KF_);
    reduce_split<<<(T_*N_ + 255)/256, 256>>>(Cs, X, X_h, X_l, T_*N_, 8);

    // ---- QX = X @ Qt^T   (z=4, 3-prod) ----
    gemm_mma<3,0><<<dim3(N_/128, T_/128, 4), 256>>>(X_h, X_l, Qt_h, Qt_l,
                                                    Cs, nullptr, nullptr, T_, N_, N_);
    reduce_epi<<<(T_*N_ + 255)/256, 256>>>(Cs, QX, nullptr, T_*N_, 4, 0);

    // ---- RU = u @ Rt^T   (z=4, 3-prod) ----
    gemm_mma<3,0><<<dim3(MC_/128, T_/128, 4), 256>>>(u_h, u_l, Rt_h, Rt_l,
                                                     Cs, nullptr, nullptr, T_, MC_, MC_);
    reduce_epi<<<(T_*MC_ + 255)/256, 256>>>(Cs, RU, nullptr, T_*MC_, 4, 0);

    // ---- losses ----
    losses_k<<<T_, 256>>>(X, QX, ufin, RU, out);
}